// round 2
// baseline (speedup 1.0000x reference)
#include <cuda_runtime.h>
#include <cstdint>

#define CIN 128
#define COUT 256
#define HW2 64
#define K_SEL 64
#define NOISE_SCALE (8.0f/255.0f)

typedef unsigned long long u64;

__device__ float g_bias[COUT];

// ---------------- bias kernel: g_bias[c] = sum |w[c,:,:,:]| ----------------
__global__ void bias_kernel(const float* __restrict__ w) {
    int c = blockIdx.x;
    int t = threadIdx.x;          // 128 threads
    float s = 0.f;
    #pragma unroll
    for (int k = 0; k < 9; k++) s += fabsf(w[c * 1152 + k * 128 + t]);
    __shared__ float red[128];
    red[t] = s;
    __syncthreads();
    #pragma unroll
    for (int off = 64; off > 0; off >>= 1) {
        if (t < off) red[t] += red[t + off];
        __syncthreads();
    }
    if (t == 0) g_bias[c] = red[0];
}

// ---------------- f32x2 helpers (Blackwell packed fp32) ----------------
__device__ __forceinline__ u64 pack2(float lo, float hi) {
    u64 r; asm("mov.b64 %0, {%1,%2};" : "=l"(r) : "f"(lo), "f"(hi)); return r;
}
__device__ __forceinline__ u64 bc2(float v) {
    u64 r; asm("mov.b64 %0, {%1,%1};" : "=l"(r) : "f"(v)); return r;
}
__device__ __forceinline__ u64 fma2(u64 a, u64 b, u64 c) {
    u64 d; asm("fma.rn.f32x2 %0, %1, %2, %3;" : "=l"(d) : "l"(a), "l"(b), "l"(c)); return d;
}
__device__ __forceinline__ void unpack2(u64 v, float& lo, float& hi) {
    asm("mov.b64 {%0,%1}, %2;" : "=f"(lo), "=f"(hi) : "l"(v));
}

__device__ __forceinline__ unsigned ordmap(float f) {
    int s = __float_as_int(f);
    return (unsigned)(s ^ ((s >> 31) | 0x80000000));
}

// smem layout (floats): xs[3*128*66] | os[64*257] | th[64] (as unsigned)
#define XS_FLOATS (3 * CIN * 66)
#define OS_FLOATS (64 * 257)
#define SMEM_FLOATS (XS_FLOATS + OS_FLOATS + 64)
#define SMEM_BYTES (SMEM_FLOATS * 4)

// ---------------- main fused kernel: one CTA per (b, h) row ----------------
__global__ __launch_bounds__(512, 1)
void topkblock_kernel(const float* __restrict__ x,
                      const float* __restrict__ weight,
                      const float* __restrict__ relu_bias,
                      const float* __restrict__ noise,
                      float* __restrict__ out) {
    extern __shared__ float sm[];
    float* xs = sm;                          // [ky][cin][66]
    float* os = sm + XS_FLOATS;              // [w][257] (channel-padded)
    unsigned* th = (unsigned*)(sm + XS_FLOATS + OS_FLOATS);   // [64]

    const int bh = blockIdx.x;
    const int b = bh >> 6;
    const int h = bh & 63;
    const int tid = threadIdx.x;

    // ---- load x halo tile into smem ----
    #pragma unroll
    for (int ky = 0; ky < 3; ky++) {
        const int hh = h - 1 + ky;
        float* xr = xs + ky * (CIN * 66);
        if (hh >= 0 && hh < 64) {
            const float* gx = x + (size_t)b * CIN * 4096 + hh * 64;
            for (int idx = tid; idx < CIN * 64; idx += 512) {
                int cin = idx >> 6, w = idx & 63;
                xr[cin * 66 + w + 1] = gx[cin * 4096 + w];
            }
            for (int cin = tid; cin < CIN; cin += 512) {
                xr[cin * 66] = 0.f;
                xr[cin * 66 + 65] = 0.f;
            }
        } else {
            for (int idx = tid; idx < CIN * 66; idx += 512) xr[idx] = 0.f;
        }
    }
    __syncthreads();

    // ---- conv: thread = (channel pair, pixel quarter), f32x2 accumulators ----
    const int pair = tid >> 2;          // 0..127
    const int q = tid & 3;              // 0..3
    const int c0 = pair * 2;
    const int bw = q * 16;

    u64 acc[16];
    #pragma unroll
    for (int p = 0; p < 16; p++) acc[p] = 0ULL;

    const float* wbase = weight + (size_t)c0 * 1152;

    #pragma unroll 1
    for (int cin = 0; cin < CIN; cin++) {
        const float* wp = wbase + cin * 9;
        u64 w2[9];
        #pragma unroll
        for (int j = 0; j < 9; j++) w2[j] = pack2(wp[j], wp[j + 1152]);

        #pragma unroll
        for (int ky = 0; ky < 3; ky++) {
            const float* xr = xs + (ky * CIN + cin) * 66 + bw;
            u64 a = bc2(xr[0]);
            u64 bb = bc2(xr[1]);
            #pragma unroll
            for (int p = 0; p < 16; p++) {
                u64 cc = bc2(xr[p + 2]);
                acc[p] = fma2(w2[ky * 3 + 0], a, acc[p]);
                acc[p] = fma2(w2[ky * 3 + 1], bb, acc[p]);
                acc[p] = fma2(w2[ky * 3 + 2], cc, acc[p]);
                a = bb;
                bb = cc;
            }
        }
    }

    // ---- dump conv results to smem (pixel-major, pad 257) ----
    #pragma unroll
    for (int p = 0; p < 16; p++) {
        float lo, hi;
        unpack2(acc[p], lo, hi);
        os[(bw + p) * 257 + c0] = lo;
        os[(bw + p) * 257 + c0 + 1] = hi;
    }
    __syncthreads();

    // ---- noise add (coalesced gmem, conflict-free smem via 257 pad) ----
    {
        const float* nb = noise + (size_t)b * COUT * 4096 + h * 64;
        for (int idx = tid; idx < COUT * 64; idx += 512) {
            int c = idx >> 6, w = idx & 63;
            float u = nb[c * 4096 + w];
            os[w * 257 + c] += g_bias[c] * NOISE_SCALE * (2.0f * u - 1.0f);
        }
    }
    __syncthreads();

    // ---- per-pixel 64th-largest via 32-step bitwise radix select ----
    {
        const int wp = tid >> 5;
        const int lane = tid & 31;
        #pragma unroll 1
        for (int pp = 0; pp < 4; pp++) {
            int p = wp * 4 + pp;
            unsigned uv[8];
            #pragma unroll
            for (int j = 0; j < 8; j++)
                uv[j] = ordmap(os[p * 257 + lane * 8 + j]);

            unsigned X = 0;
            #pragma unroll 1
            for (int bit = 31; bit >= 0; bit--) {
                unsigned cand = X | (1u << bit);
                int cnt = 0;
                #pragma unroll
                for (int j = 0; j < 8; j++) cnt += (uv[j] >= cand) ? 1 : 0;
                int tot = __reduce_add_sync(0xffffffffu, cnt);
                if (tot >= K_SEL) X = cand;
            }
            if (lane == 0) th[p] = X;
        }
    }
    __syncthreads();

    // ---- threshold + relu_bias + relu, coalesced store ----
    {
        float* ob = out + (size_t)b * COUT * 4096 + h * 64;
        for (int idx = tid; idx < COUT * 64; idx += 512) {
            int c = idx >> 6, w = idx & 63;
            float v = os[w * 257 + c];
            unsigned u = ordmap(v);
            float keep = (u >= th[w]) ? v : 0.f;
            float r = keep + __ldg(relu_bias + c);
            ob[c * 4096 + w] = fmaxf(r, 0.f);
        }
    }
}

// ---------------- launch ----------------
extern "C" void kernel_launch(void* const* d_in, const int* in_sizes, int n_in,
                              void* d_out, int out_size) {
    const float* x         = (const float*)d_in[0];
    const float* weight    = (const float*)d_in[1];
    const float* relu_bias = (const float*)d_in[2];
    const float* noise     = (const float*)d_in[3];
    float* out = (float*)d_out;

    bias_kernel<<<COUT, 128>>>(weight);

    cudaFuncSetAttribute(topkblock_kernel,
                         cudaFuncAttributeMaxDynamicSharedMemorySize, SMEM_BYTES);
    topkblock_kernel<<<32 * 64, 512, SMEM_BYTES>>>(x, weight, relu_bias, noise, out);
}

// round 6
// speedup vs baseline: 2.0971x; 2.0971x over previous
#include <cuda_runtime.h>
#include <cuda_fp16.h>
#include <cstdint>

#define NOISE_SCALE (8.0f/255.0f)
#define K_SEL 64

__device__ float g_bias[256];
__device__ __half g_Aexp[2 * 9 * 256 * 128];   // [comp][kk][cout][cin]; comp0=w_hi, comp1=(w-w_hi)*2048

// ---------------- smem layout (bytes) ----------------
#define SM_A   1024                      // A' : 256 rows x 512B (K=256 halves)  = 128KB
#define SM_B   (SM_A + 131072)           // B' : 256 rows x 128B (N=64 halves)   = 32KB
#define SM_B1  (SM_B + 32768)            // Blo: 128 rows x 128B                 = 16KB
#define SMEM_BYTES (SM_B1 + 16384 + 256) // 181504
#define OS_OFF 1024                      // overlay os[64][257] f32 on dead A'
#define TH_OFF (OS_OFF + 64 * 257 * 4)

__device__ __forceinline__ uint32_t smem_u32(const void* p) {
    uint32_t a;
    asm("{ .reg .u64 t; cvta.to.shared.u64 t, %1; cvt.u32.u64 %0, t; }" : "=r"(a) : "l"(p));
    return a;
}
__device__ __forceinline__ unsigned ordmap(float f) {
    int s = __float_as_int(f);
    return (unsigned)(s ^ ((s >> 31) | 0x80000000));
}
__device__ __forceinline__ uint32_t h2u(__half2 h) {
    uint32_t u; __builtin_memcpy(&u, &h, 4); return u;
}

#define LDMX4(r0,r1,r2,r3,ad) \
    asm volatile("ldmatrix.sync.aligned.m8n8.x4.shared.b16 {%0,%1,%2,%3}, [%4];" \
        : "=r"(r0),"=r"(r1),"=r"(r2),"=r"(r3) : "r"(ad))
#define LDMX4T(r0,r1,r2,r3,ad) \
    asm volatile("ldmatrix.sync.aligned.m8n8.x4.trans.shared.b16 {%0,%1,%2,%3}, [%4];" \
        : "=r"(r0),"=r"(r1),"=r"(r2),"=r"(r3) : "r"(ad))
#define MMA16816(c, a, b0v, b1v) \
    asm volatile("mma.sync.aligned.m16n8k16.row.col.f32.f16.f16.f32 " \
        "{%0,%1,%2,%3}, {%4,%5,%6,%7}, {%8,%9}, {%0,%1,%2,%3};" \
        : "+f"((c)[0]), "+f"((c)[1]), "+f"((c)[2]), "+f"((c)[3]) \
        : "r"((a)[0]), "r"((a)[1]), "r"((a)[2]), "r"((a)[3]), "r"(b0v), "r"(b1v))

// ---------------- prep: g_bias[c] = sum |w[c,:,:,:]| ----------------
__global__ void bias_kernel(const float* __restrict__ w) {
    int c = blockIdx.x, t = threadIdx.x;
    float s = 0.f;
    #pragma unroll
    for (int k = 0; k < 9; k++) s += fabsf(w[c * 1152 + k * 128 + t]);
    __shared__ float red[128];
    red[t] = s;
    __syncthreads();
    #pragma unroll
    for (int off = 64; off > 0; off >>= 1) {
        if (t < off) red[t] += red[t + off];
        __syncthreads();
    }
    if (t == 0) g_bias[c] = red[0];
}

// ---------------- prep: fp16 hi/lo split weights ----------------
__global__ void wexpand_kernel(const float* __restrict__ w) {
    int co = blockIdx.x;
    for (int idx = threadIdx.x; idx < 1152; idx += blockDim.x) {
        int kk = idx >> 7, cin = idx & 127;
        float v = w[co * 1152 + cin * 9 + kk];
        __half hi = __float2half_rn(v);
        __half lo = __float2half_rn((v - __half2float(hi)) * 2048.0f);
        g_Aexp[((size_t)kk * 256 + co) * 128 + cin] = hi;
        g_Aexp[(size_t)9 * 256 * 128 + ((size_t)kk * 256 + co) * 128 + cin] = lo;
    }
}

// ---------------- fused conv (3-product fp16 mma) + noise + topk + relu -----
__global__ __launch_bounds__(512, 1)
void conv_topk_kernel(const float* __restrict__ x,
                      const float* __restrict__ noise,
                      const float* __restrict__ relu_bias,
                      float* __restrict__ out) {
    extern __shared__ char smem[];
    const uint32_t sb = smem_u32(smem);
    const int tid = threadIdx.x;
    const int wid = tid >> 5, lane = tid & 31;
    const int wm = wid & 7, wn = wid >> 3;       // 8 M-warps x 2 N-warps
    const int b = blockIdx.x >> 6;
    const int h0 = blockIdx.x & 63;

    float acc_hi[2][4][4], acc_lo[2][4][4];
    #pragma unroll
    for (int i = 0; i < 2; i++)
        #pragma unroll
        for (int j = 0; j < 4; j++)
            #pragma unroll
            for (int k = 0; k < 4; k++) { acc_hi[i][j][k] = 0.f; acc_lo[i][j][k] = 0.f; }

    const int mlA = lane & 15, kbA = lane >> 4;
    const int klB = lane & 15, nbB = lane >> 4;

    // staging roles
    const int am = tid >> 1, aq = tid & 1;         // A: row am, comp aq
    const int scin = tid & 127;                    // B: k row
    const int nseg = (tid >> 7) & 3;               // B: 16-wide n segment
    const int n0 = nseg * 16;

    const __half2 S2 = __half2half2(__float2half_rn(4.8828125e-4f));  // 2^-11

    #pragma unroll 1
    for (int kk = 0; kk < 9; kk++) {
        const int ky = kk / 3, kx = kk % 3;
        __syncthreads();   // previous iteration's MMA reads complete

        // ---- stage A' [256m][256k]: k0-127 = w_hi, k128-255 = w_lo*2^11 ----
        {
            const __half* Ac = g_Aexp + ((size_t)(aq * 9 + kk) * 256 + am) * 128;
            #pragma unroll
            for (int j = 0; j < 16; j++) {
                uint4 v = *(const uint4*)(Ac + j * 8);
                const uint32_t c16 = (uint32_t)((aq * 16 + j) ^ (am & 7));
                *(uint4*)(smem + SM_A + am * 512 + c16 * 16) = v;
            }
        }

        // ---- stage B' (x_hi rows 0-127, x_hi*2^-11 rows 128-255) + Blo ----
        {
            const int hh = h0 + ky - 1;
            const bool valid = (hh >= 0) && (hh < 64);
            float q[16], lft = 0.f, rgt = 0.f;
            if (valid) {
                const float* rp = x + (((size_t)b * 128 + scin) * 64 + hh) * 64;
                #pragma unroll
                for (int j = 0; j < 4; j++) {
                    float4 v = *(const float4*)(rp + n0 + j * 4);
                    q[j*4+0] = v.x; q[j*4+1] = v.y; q[j*4+2] = v.z; q[j*4+3] = v.w;
                }
                lft = (n0 > 0) ? rp[n0 - 1] : 0.f;
                rgt = (n0 + 16 < 64) ? rp[n0 + 16] : 0.f;
            } else {
                #pragma unroll
                for (int j = 0; j < 16; j++) q[j] = 0.f;
            }
            float f[16];
            if (kx == 1) {
                #pragma unroll
                for (int i = 0; i < 16; i++) f[i] = q[i];
            } else if (kx == 0) {
                f[0] = lft;
                #pragma unroll
                for (int i = 1; i < 16; i++) f[i] = q[i - 1];
            } else {
                #pragma unroll
                for (int i = 0; i < 15; i++) f[i] = q[i + 1];
                f[15] = rgt;
            }
            uint32_t hiu[8], hsu[8], lou[8];
            #pragma unroll
            for (int i = 0; i < 8; i++) {
                __half a0 = __float2half_rn(f[2*i]);
                __half a1 = __float2half_rn(f[2*i+1]);
                __half2 hh2 = __halves2half2(a0, a1);
                hiu[i] = h2u(hh2);
                hsu[i] = h2u(__hmul2(hh2, S2));
                __half l0 = __float2half_rn((f[2*i]   - __half2float(a0)) * 2048.0f);
                __half l1 = __float2half_rn((f[2*i+1] - __half2float(a1)) * 2048.0f);
                lou[i] = h2u(__halves2half2(l0, l1));
            }
            const uint32_t c16a = (uint32_t)((2 * nseg) ^ (scin & 7));
            const uint32_t c16b = (uint32_t)((2 * nseg + 1) ^ (scin & 7));
            *(uint4*)(smem + SM_B + scin * 128 + c16a * 16) = make_uint4(hiu[0], hiu[1], hiu[2], hiu[3]);
            *(uint4*)(smem + SM_B + scin * 128 + c16b * 16) = make_uint4(hiu[4], hiu[5], hiu[6], hiu[7]);
            *(uint4*)(smem + SM_B + (scin + 128) * 128 + c16a * 16) = make_uint4(hsu[0], hsu[1], hsu[2], hsu[3]);
            *(uint4*)(smem + SM_B + (scin + 128) * 128 + c16b * 16) = make_uint4(hsu[4], hsu[5], hsu[6], hsu[7]);
            *(uint4*)(smem + SM_B1 + scin * 128 + c16a * 16) = make_uint4(lou[0], lou[1], lou[2], lou[3]);
            *(uint4*)(smem + SM_B1 + scin * 128 + c16b * 16) = make_uint4(lou[4], lou[5], lou[6], lou[7]);
        }
        __syncthreads();

        // ---- pass 0: K=256 (w_hi·x_hi + w_lo·x_hi) -> acc_hi ----
        #pragma unroll
        for (int ks = 0; ks < 16; ks++) {
            uint32_t a[2][4];
            #pragma unroll
            for (int mt = 0; mt < 2; mt++) {
                const int m = wm * 32 + mt * 16 + mlA;
                const uint32_t c16 = (uint32_t)((ks * 2 + kbA) ^ (m & 7));
                LDMX4(a[mt][0], a[mt][1], a[mt][2], a[mt][3], sb + SM_A + m * 512 + c16 * 16);
            }
            const int k = ks * 16 + klB;
            #pragma unroll
            for (int ntp = 0; ntp < 2; ntp++) {
                const uint32_t c16 = (uint32_t)((wn * 4 + ntp * 2 + nbB) ^ (k & 7));
                uint32_t bb[4];
                LDMX4T(bb[0], bb[1], bb[2], bb[3], sb + SM_B + k * 128 + c16 * 16);
                MMA16816(acc_hi[0][ntp * 2],     a[0], bb[0], bb[1]);
                MMA16816(acc_hi[0][ntp * 2 + 1], a[0], bb[2], bb[3]);
                MMA16816(acc_hi[1][ntp * 2],     a[1], bb[0], bb[1]);
                MMA16816(acc_hi[1][ntp * 2 + 1], a[1], bb[2], bb[3]);
            }
        }
        // ---- pass 1: K=128 (w_hi·x_lo*2^11) -> acc_lo ----
        #pragma unroll
        for (int ks = 0; ks < 8; ks++) {
            uint32_t a[2][4];
            #pragma unroll
            for (int mt = 0; mt < 2; mt++) {
                const int m = wm * 32 + mt * 16 + mlA;
                const uint32_t c16 = (uint32_t)((ks * 2 + kbA) ^ (m & 7));
                LDMX4(a[mt][0], a[mt][1], a[mt][2], a[mt][3], sb + SM_A + m * 512 + c16 * 16);
            }
            const int k = ks * 16 + klB;
            #pragma unroll
            for (int ntp = 0; ntp < 2; ntp++) {
                const uint32_t c16 = (uint32_t)((wn * 4 + ntp * 2 + nbB) ^ (k & 7));
                uint32_t bb[4];
                LDMX4T(bb[0], bb[1], bb[2], bb[3], sb + SM_B1 + k * 128 + c16 * 16);
                MMA16816(acc_lo[0][ntp * 2],     a[0], bb[0], bb[1]);
                MMA16816(acc_lo[0][ntp * 2 + 1], a[0], bb[2], bb[3]);
                MMA16816(acc_lo[1][ntp * 2],     a[1], bb[0], bb[1]);
                MMA16816(acc_lo[1][ntp * 2 + 1], a[1], bb[2], bb[3]);
            }
        }
    }

    // ---- epilogue: combine + overlay os[64][257] on dead A' ----
    __syncthreads();
    float* os = (float*)(smem + OS_OFF);
    unsigned* th = (unsigned*)(smem + TH_OFF);
    const float RS = 4.8828125e-4f;   // 2^-11

    #pragma unroll
    for (int mt = 0; mt < 2; mt++) {
        const int co = wm * 32 + mt * 16 + (lane >> 2);
        #pragma unroll
        for (int nt = 0; nt < 4; nt++) {
            const int n = wn * 32 + nt * 8 + (lane & 3) * 2;
            os[n * 257 + co]           = acc_hi[mt][nt][0] + acc_lo[mt][nt][0] * RS;
            os[(n + 1) * 257 + co]     = acc_hi[mt][nt][1] + acc_lo[mt][nt][1] * RS;
            os[n * 257 + co + 8]       = acc_hi[mt][nt][2] + acc_lo[mt][nt][2] * RS;
            os[(n + 1) * 257 + co + 8] = acc_hi[mt][nt][3] + acc_lo[mt][nt][3] * RS;
        }
    }
    __syncthreads();

    // noise add
    {
        const float* nb = noise + (size_t)b * 256 * 4096 + h0 * 64;
        for (int idx = tid; idx < 256 * 64; idx += 512) {
            int c = idx >> 6, w = idx & 63;
            float u = nb[c * 4096 + w];
            os[w * 257 + c] += g_bias[c] * NOISE_SCALE * (2.0f * u - 1.0f);
        }
    }
    __syncthreads();

    // per-pixel 64th-largest via 32-step bitwise radix select (1 warp/pixel)
    #pragma unroll 1
    for (int pp = 0; pp < 4; pp++) {
        const int p = wid * 4 + pp;
        unsigned uv[8];
        #pragma unroll
        for (int j = 0; j < 8; j++)
            uv[j] = ordmap(os[p * 257 + lane * 8 + j]);
        unsigned X = 0;
        #pragma unroll 1
        for (int bit = 31; bit >= 0; bit--) {
            unsigned cand = X | (1u << bit);
            int cnt = 0;
            #pragma unroll
            for (int j = 0; j < 8; j++) cnt += (uv[j] >= cand) ? 1 : 0;
            int tot = __reduce_add_sync(0xffffffffu, cnt);
            if (tot >= K_SEL) X = cand;
        }
        if (lane == 0) th[p] = X;
    }
    __syncthreads();

    // threshold + relu_bias + relu, coalesced store
    {
        float* ob = out + (size_t)b * 256 * 4096 + h0 * 64;
        for (int idx = tid; idx < 256 * 64; idx += 512) {
            int c = idx >> 6, w = idx & 63;
            float v = os[w * 257 + c];
            float keep = (ordmap(v) >= th[w]) ? v : 0.f;
            ob[c * 4096 + w] = fmaxf(keep + __ldg(relu_bias + c), 0.f);
        }
    }
}

// ---------------- launch ----------------
extern "C" void kernel_launch(void* const* d_in, const int* in_sizes, int n_in,
                              void* d_out, int out_size) {
    const float* x         = (const float*)d_in[0];
    const float* weight    = (const float*)d_in[1];
    const float* relu_bias = (const float*)d_in[2];
    const float* noise     = (const float*)d_in[3];
    float* out = (float*)d_out;

    bias_kernel<<<256, 128>>>(weight);
    wexpand_kernel<<<256, 256>>>(weight);

    cudaFuncSetAttribute(conv_topk_kernel,
                         cudaFuncAttributeMaxDynamicSharedMemorySize, SMEM_BYTES);
    conv_topk_kernel<<<2048, 512, SMEM_BYTES>>>(x, noise, relu_bias, out);
}

// round 11
// speedup vs baseline: 2.1589x; 1.0295x over previous
#include <cuda_runtime.h>
#include <cuda_fp16.h>
#include <cstdint>

#define NOISE_SCALE (8.0f/255.0f)
#define K_SEL 64

__device__ float g_bias[256];
__device__ __half g_Aexp[2 * 9 * 256 * 128];          // [comp][kk][cout][cin]
__device__ float g_conv[(size_t)32 * 256 * 64 * 64];  // conv scratch (NCHW)

// ---------------- conv smem layout (bytes) ----------------
#define SM_A  0            // A' [128 m][256 k] halves, 512B rows  = 64KB
#define SM_B  65536        // B' [256 k][64 n] halves, 128B rows   = 32KB
#define SM_B1 98304        // B1 [128 k][64 n] halves, 128B rows   = 16KB
#define CONV_SMEM 114688   // 112KB -> 2 CTAs/SM

__device__ __forceinline__ uint32_t smem_u32(const void* p) {
    uint32_t a;
    asm("{ .reg .u64 t; cvta.to.shared.u64 t, %1; cvt.u32.u64 %0, t; }" : "=r"(a) : "l"(p));
    return a;
}
__device__ __forceinline__ unsigned ordmap(float f) {
    int s = __float_as_int(f);
    return (unsigned)(s ^ ((s >> 31) | 0x80000000));
}
__device__ __forceinline__ uint32_t h2u(__half2 h) {
    uint32_t u; __builtin_memcpy(&u, &h, 4); return u;
}

#define CP_ASYNC16(dst, src) \
    asm volatile("cp.async.ca.shared.global [%0], [%1], 16;" :: "r"(dst), "l"(src))
#define CP_COMMIT() asm volatile("cp.async.commit_group;" ::: "memory")
#define CP_WAIT0()  asm volatile("cp.async.wait_group 0;" ::: "memory")

#define LDMX4(r0,r1,r2,r3,ad) \
    asm volatile("ldmatrix.sync.aligned.m8n8.x4.shared.b16 {%0,%1,%2,%3}, [%4];" \
        : "=r"(r0),"=r"(r1),"=r"(r2),"=r"(r3) : "r"(ad))
#define LDMX4T(r0,r1,r2,r3,ad) \
    asm volatile("ldmatrix.sync.aligned.m8n8.x4.trans.shared.b16 {%0,%1,%2,%3}, [%4];" \
        : "=r"(r0),"=r"(r1),"=r"(r2),"=r"(r3) : "r"(ad))
#define MMA16816(c, a, b0v, b1v) \
    asm volatile("mma.sync.aligned.m16n8k16.row.col.f32.f16.f16.f32 " \
        "{%0,%1,%2,%3}, {%4,%5,%6,%7}, {%8,%9}, {%0,%1,%2,%3};" \
        : "+f"((c)[0]), "+f"((c)[1]), "+f"((c)[2]), "+f"((c)[3]) \
        : "r"((a)[0]), "r"((a)[1]), "r"((a)[2]), "r"((a)[3]), "r"(b0v), "r"(b1v))

// ---------------- prep: g_bias[c] = sum |w[c,:,:,:]| ----------------
__global__ void bias_kernel(const float* __restrict__ w) {
    int c = blockIdx.x, t = threadIdx.x;
    float s = 0.f;
    #pragma unroll
    for (int k = 0; k < 9; k++) s += fabsf(w[c * 1152 + k * 128 + t]);
    __shared__ float red[128];
    red[t] = s;
    __syncthreads();
    #pragma unroll
    for (int off = 64; off > 0; off >>= 1) {
        if (t < off) red[t] += red[t + off];
        __syncthreads();
    }
    if (t == 0) g_bias[c] = red[0];
}

// ---------------- prep: fp16 hi/lo split weights ----------------
__global__ void wexpand_kernel(const float* __restrict__ w) {
    int co = blockIdx.x;
    for (int idx = threadIdx.x; idx < 1152; idx += blockDim.x) {
        int kk = idx >> 7, cin = idx & 127;
        float v = w[co * 1152 + cin * 9 + kk];
        __half hi = __float2half_rn(v);
        __half lo = __float2half_rn((v - __half2float(hi)) * 2048.0f);
        g_Aexp[((size_t)kk * 256 + co) * 128 + cin] = hi;
        g_Aexp[(size_t)9 * 256 * 128 + ((size_t)kk * 256 + co) * 128 + cin] = lo;
    }
}

// ---------------- conv: 3-product fp16 mma.sync, M=128 N=64, occ 2 ----------
__global__ __launch_bounds__(256, 2)
void conv_kernel(const float* __restrict__ x) {
    extern __shared__ char smem[];
    const uint32_t sb = smem_u32(smem);
    const int tid = threadIdx.x;
    const int wid = tid >> 5, lane = tid & 31;
    const int wm = wid & 3, wn = wid >> 2;       // 4 M-warps x 2 N-warps
    const int mhalf = blockIdx.x;                // 0-1
    const int h0 = blockIdx.y;                   // 0-63
    const int b = blockIdx.z;                    // 0-31
    const int m0 = mhalf * 128;

    float acc_hi[2][4][4], acc_lo[2][4][4];
    #pragma unroll
    for (int i = 0; i < 2; i++)
        #pragma unroll
        for (int j = 0; j < 4; j++)
            #pragma unroll
            for (int k = 0; k < 4; k++) { acc_hi[i][j][k] = 0.f; acc_lo[i][j][k] = 0.f; }

    const int mlA = lane & 15, kbA = lane >> 4;
    const int klB = lane & 15, nbB = lane >> 4;

    // staging roles
    const int am = tid >> 1, aq = tid & 1;       // A: row am (0-127), comp aq
    const int scin = tid & 127, nh = tid >> 7;   // B: k row, n half
    const int n0 = nh * 32;

    const __half2 S2 = __half2half2(__float2half_rn(4.8828125e-4f));  // 2^-11

    #pragma unroll 1
    for (int kk = 0; kk < 9; kk++) {
        const int ky = kk / 3, kx = kk % 3;
        __syncthreads();   // previous iteration's smem reads complete

        // ---- stage A' [128 m][256 k] via cp.async (k0-127 w_hi, k128-255 w_lo*2^11) ----
        {
            const __half* Ac = g_Aexp + ((size_t)(aq * 9 + kk) * 256 + m0 + am) * 128;
            #pragma unroll
            for (int j = 0; j < 16; j++) {
                const uint32_t dst = sb + SM_A + am * 512 +
                                     (uint32_t)(((aq * 16 + j) ^ (am & 7)) * 16);
                CP_ASYNC16(dst, Ac + j * 8);
            }
            CP_COMMIT();
        }

        // ---- stage B (rolling 8-float window; low register pressure) ----
        {
            const int hh = h0 + ky - 1;
            const bool valid = (hh >= 0) && (hh < 64);
            const float* rp = x + (((size_t)b * 128 + scin) * 64 + hh) * 64;
            float prv = (valid && n0 > 0) ? rp[n0 - 1] : 0.f;
            #pragma unroll
            for (int j = 0; j < 4; j++) {
                float g[8], nxt;
                if (valid) {
                    float4 v0 = *(const float4*)(rp + n0 + j * 8);
                    float4 v1 = *(const float4*)(rp + n0 + j * 8 + 4);
                    g[0]=v0.x; g[1]=v0.y; g[2]=v0.z; g[3]=v0.w;
                    g[4]=v1.x; g[5]=v1.y; g[6]=v1.z; g[7]=v1.w;
                    nxt = (n0 + j * 8 + 8 < 64) ? rp[n0 + j * 8 + 8] : 0.f;
                } else {
                    #pragma unroll
                    for (int i = 0; i < 8; i++) g[i] = 0.f;
                    nxt = 0.f;
                }
                float f[8];
                if (kx == 0) {
                    f[0] = prv;
                    #pragma unroll
                    for (int i = 1; i < 8; i++) f[i] = g[i - 1];
                } else if (kx == 1) {
                    #pragma unroll
                    for (int i = 0; i < 8; i++) f[i] = g[i];
                } else {
                    #pragma unroll
                    for (int i = 0; i < 7; i++) f[i] = g[i + 1];
                    f[7] = nxt;
                }
                prv = g[7];
                uint32_t hiu[4], hsu[4], lou[4];
                #pragma unroll
                for (int i = 0; i < 4; i++) {
                    __half a0 = __float2half_rn(f[2 * i]);
                    __half a1 = __float2half_rn(f[2 * i + 1]);
                    __half2 hh2 = __halves2half2(a0, a1);
                    hiu[i] = h2u(hh2);
                    hsu[i] = h2u(__hmul2(hh2, S2));
                    __half l0 = __float2half_rn((f[2 * i]     - __half2float(a0)) * 2048.0f);
                    __half l1 = __float2half_rn((f[2 * i + 1] - __half2float(a1)) * 2048.0f);
                    lou[i] = h2u(__halves2half2(l0, l1));
                }
                const uint32_t c16 = (uint32_t)((nh * 4 + j) ^ (scin & 7));
                *(uint4*)(smem + SM_B  + scin * 128 + c16 * 16)         = make_uint4(hiu[0], hiu[1], hiu[2], hiu[3]);
                *(uint4*)(smem + SM_B  + (scin + 128) * 128 + c16 * 16) = make_uint4(hsu[0], hsu[1], hsu[2], hsu[3]);
                *(uint4*)(smem + SM_B1 + scin * 128 + c16 * 16)         = make_uint4(lou[0], lou[1], lou[2], lou[3]);
            }
        }
        CP_WAIT0();
        __syncthreads();

        // ---- merged MMA: ks 0-15 -> acc_hi (K=256); ks 0-7 also -> acc_lo ----
        #pragma unroll
        for (int ks = 0; ks < 16; ks++) {
            uint32_t a[2][4];
            #pragma unroll
            for (int mt = 0; mt < 2; mt++) {
                const int m = wm * 32 + mt * 16 + mlA;
                const uint32_t c16 = (uint32_t)((ks * 2 + kbA) ^ (m & 7));
                LDMX4(a[mt][0], a[mt][1], a[mt][2], a[mt][3], sb + SM_A + m * 512 + c16 * 16);
            }
            const int k = ks * 16 + klB;
            #pragma unroll
            for (int ntp = 0; ntp < 2; ntp++) {
                const uint32_t c16 = (uint32_t)((wn * 4 + ntp * 2 + nbB) ^ (k & 7));
                uint32_t bb[4];
                LDMX4T(bb[0], bb[1], bb[2], bb[3], sb + SM_B + k * 128 + c16 * 16);
                MMA16816(acc_hi[0][ntp * 2],     a[0], bb[0], bb[1]);
                MMA16816(acc_hi[0][ntp * 2 + 1], a[0], bb[2], bb[3]);
                MMA16816(acc_hi[1][ntp * 2],     a[1], bb[0], bb[1]);
                MMA16816(acc_hi[1][ntp * 2 + 1], a[1], bb[2], bb[3]);
            }
            if (ks < 8) {
                #pragma unroll
                for (int ntp = 0; ntp < 2; ntp++) {
                    const uint32_t c16 = (uint32_t)((wn * 4 + ntp * 2 + nbB) ^ (k & 7));
                    uint32_t bb[4];
                    LDMX4T(bb[0], bb[1], bb[2], bb[3], sb + SM_B1 + k * 128 + c16 * 16);
                    MMA16816(acc_lo[0][ntp * 2],     a[0], bb[0], bb[1]);
                    MMA16816(acc_lo[0][ntp * 2 + 1], a[0], bb[2], bb[3]);
                    MMA16816(acc_lo[1][ntp * 2],     a[1], bb[0], bb[1]);
                    MMA16816(acc_lo[1][ntp * 2 + 1], a[1], bb[2], bb[3]);
                }
            }
        }
    }

    // ---- epilogue: combine hi/lo and write conv scratch ----
    const float RS = 4.8828125e-4f;   // 2^-11
    #pragma unroll
    for (int mt = 0; mt < 2; mt++) {
        const int co = m0 + wm * 32 + mt * 16 + (lane >> 2);
        float* dst = g_conv + (((size_t)b * 256 + co) * 64 + h0) * 64;
        #pragma unroll
        for (int nt = 0; nt < 4; nt++) {
            const int n = wn * 32 + nt * 8 + (lane & 3) * 2;
            float2 v01 = make_float2(acc_hi[mt][nt][0] + acc_lo[mt][nt][0] * RS,
                                     acc_hi[mt][nt][1] + acc_lo[mt][nt][1] * RS);
            float2 v23 = make_float2(acc_hi[mt][nt][2] + acc_lo[mt][nt][2] * RS,
                                     acc_hi[mt][nt][3] + acc_lo[mt][nt][3] * RS);
            *(float2*)(dst + n) = v01;
            *(float2*)(dst + 8 * 4096 + n) = v23;   // co + 8
        }
    }
}

// ---------------- topk: noise + 64th-largest + bias + relu ----------------
#define OS_FLOATS (64 * 257)
#define TOPK_SMEM ((OS_FLOATS + 64) * 4)

__global__ __launch_bounds__(512, 1)
void topk_kernel(const float* __restrict__ noise,
                 const float* __restrict__ relu_bias,
                 float* __restrict__ out) {
    extern __shared__ float sm[];
    float* os = sm;                                  // [w][257]
    unsigned* th = (unsigned*)(sm + OS_FLOATS);      // [64]

    const int bh = blockIdx.x;
    const int b = bh >> 6;
    const int h = bh & 63;
    const int tid = threadIdx.x;
    const int wid = tid >> 5, lane = tid & 31;

    // load conv + noise add (coalesced)
    {
        const float* cb = g_conv + (size_t)b * 256 * 4096 + h * 64;
        const float* nb = noise + (size_t)b * 256 * 4096 + h * 64;
        for (int idx = tid; idx < 256 * 64; idx += 512) {
            int c = idx >> 6, w = idx & 63;
            float u = nb[c * 4096 + w];
            os[w * 257 + c] = cb[c * 4096 + w] + g_bias[c] * NOISE_SCALE * (2.0f * u - 1.0f);
        }
    }
    __syncthreads();

    // per-pixel 64th-largest via 32-step bitwise radix select (1 warp/pixel)
    #pragma unroll 1
    for (int pp = 0; pp < 4; pp++) {
        const int p = wid * 4 + pp;
        unsigned uv[8];
        #pragma unroll
        for (int j = 0; j < 8; j++)
            uv[j] = ordmap(os[p * 257 + lane * 8 + j]);
        unsigned X = 0;
        #pragma unroll 1
        for (int bit = 31; bit >= 0; bit--) {
            unsigned cand = X | (1u << bit);
            int cnt = 0;
            #pragma unroll
            for (int j = 0; j < 8; j++) cnt += (uv[j] >= cand) ? 1 : 0;
            int tot = __reduce_add_sync(0xffffffffu, cnt);
            if (tot >= K_SEL) X = cand;
        }
        if (lane == 0) th[p] = X;
    }
    __syncthreads();

    // threshold + relu_bias + relu, coalesced store
    {
        float* ob = out + (size_t)b * 256 * 4096 + h * 64;
        for (int idx = tid; idx < 256 * 64; idx += 512) {
            int c = idx >> 6, w = idx & 63;
            float v = os[w * 257 + c];
            float keep = (ordmap(v) >= th[w]) ? v : 0.f;
            ob[c * 4096 + w] = fmaxf(keep + __ldg(relu_bias + c), 0.f);
        }
    }
}

// ---------------- launch ----------------
extern "C" void kernel_launch(void* const* d_in, const int* in_sizes, int n_in,
                              void* d_out, int out_size) {
    const float* x         = (const float*)d_in[0];
    const float* weight    = (const float*)d_in[1];
    const float* relu_bias = (const float*)d_in[2];
    const float* noise     = (const float*)d_in[3];
    float* out = (float*)d_out;

    bias_kernel<<<256, 128>>>(weight);
    wexpand_kernel<<<256, 256>>>(weight);

    cudaFuncSetAttribute(conv_kernel,
                         cudaFuncAttributeMaxDynamicSharedMemorySize, CONV_SMEM);
    conv_kernel<<<dim3(2, 64, 32), 256, CONV_SMEM>>>(x);

    cudaFuncSetAttribute(topk_kernel,
                         cudaFuncAttributeMaxDynamicSharedMemorySize, TOPK_SMEM);
    topk_kernel<<<2048, 512, TOPK_SMEM>>>(noise, relu_bias, out);
}

// round 12
// speedup vs baseline: 2.5287x; 1.1712x over previous
#include <cuda_runtime.h>
#include <cuda_fp16.h>
#include <cstdint>

#define NOISE_SCALE (8.0f/255.0f)
#define K_SEL 64

__device__ float g_bias[256];
__device__ __half g_Aexp[2 * 9 * 256 * 128];          // [comp][kk][cout][cin]
__device__ float g_conv[(size_t)32 * 256 * 64 * 64];  // conv scratch (NCHW)

// ---------------- conv smem layout (bytes) ----------------
// A: double-buffered [128 m][256 k] halves, 512B rows, 64KB each
#define SM_XH  131072                 // xh: 193 rows x 256B (row 0 = zeros)
#define SM_XL  180480                 // xl': 193 rows x 256B
#define XL_DELTA 49408                // SM_XL - SM_XH
#define CONV_SMEM 229888              // 224.5KB

__device__ __forceinline__ uint32_t smem_u32(const void* p) {
    uint32_t a;
    asm("{ .reg .u64 t; cvta.to.shared.u64 t, %1; cvt.u32.u64 %0, t; }" : "=r"(a) : "l"(p));
    return a;
}
__device__ __forceinline__ unsigned ordmap(float f) {
    int s = __float_as_int(f);
    return (unsigned)(s ^ ((s >> 31) | 0x80000000));
}

#define CP_ASYNC16(dst, src) \
    asm volatile("cp.async.ca.shared.global [%0], [%1], 16;" :: "r"(dst), "l"(src))
#define CP_COMMIT() asm volatile("cp.async.commit_group;" ::: "memory")
#define CP_WAIT0()  asm volatile("cp.async.wait_group 0;" ::: "memory")

#define LDMX4(r0,r1,r2,r3,ad) \
    asm volatile("ldmatrix.sync.aligned.m8n8.x4.shared.b16 {%0,%1,%2,%3}, [%4];" \
        : "=r"(r0),"=r"(r1),"=r"(r2),"=r"(r3) : "r"(ad))
#define MMA16816(c, a, b0v, b1v) \
    asm volatile("mma.sync.aligned.m16n8k16.row.col.f32.f16.f16.f32 " \
        "{%0,%1,%2,%3}, {%4,%5,%6,%7}, {%8,%9}, {%0,%1,%2,%3};" \
        : "+f"((c)[0]), "+f"((c)[1]), "+f"((c)[2]), "+f"((c)[3]) \
        : "r"((a)[0]), "r"((a)[1]), "r"((a)[2]), "r"((a)[3]), "r"(b0v), "r"(b1v))

// ---------------- prep: g_bias[c] = sum |w[c,:,:,:]| ----------------
__global__ void bias_kernel(const float* __restrict__ w) {
    int c = blockIdx.x, t = threadIdx.x;
    float s = 0.f;
    #pragma unroll
    for (int k = 0; k < 9; k++) s += fabsf(w[c * 1152 + k * 128 + t]);
    __shared__ float red[128];
    red[t] = s;
    __syncthreads();
    #pragma unroll
    for (int off = 64; off > 0; off >>= 1) {
        if (t < off) red[t] += red[t + off];
        __syncthreads();
    }
    if (t == 0) g_bias[c] = red[0];
}

// ---------------- prep: fp16 hi/lo split weights ----------------
__global__ void wexpand_kernel(const float* __restrict__ w) {
    int co = blockIdx.x;
    for (int idx = threadIdx.x; idx < 1152; idx += blockDim.x) {
        int kk = idx >> 7, cin = idx & 127;
        float v = w[co * 1152 + cin * 9 + kk];
        __half hi = __float2half_rn(v);
        __half lo = __float2half_rn((v - __half2float(hi)) * 2048.0f);
        g_Aexp[((size_t)kk * 256 + co) * 128 + cin] = hi;
        g_Aexp[(size_t)9 * 256 * 128 + ((size_t)kk * 256 + co) * 128 + cin] = lo;
    }
}

// ---------------- conv: stage-once-B fp16 mma.sync ----------------
__global__ __launch_bounds__(256, 1)
void conv_kernel(const float* __restrict__ x) {
    extern __shared__ char smem[];
    const uint32_t sb = smem_u32(smem);
    const int tid = threadIdx.x;
    const int wid = tid >> 5, lane = tid & 31;
    const int wm = wid & 3, wn = wid >> 2;       // 4 M-warps x 2 N-warps
    const int mhalf = blockIdx.x;                // 0-1
    const int h0 = blockIdx.y;                   // 0-63
    const int b = blockIdx.z;                    // 0-31
    const int m0 = mhalf * 128;

    float acc1[2][4][4], acc2[2][4][4];
    #pragma unroll
    for (int i = 0; i < 2; i++)
        #pragma unroll
        for (int j = 0; j < 4; j++)
            #pragma unroll
            for (int k = 0; k < 4; k++) { acc1[i][j][k] = 0.f; acc2[i][j][k] = 0.f; }

    const int mlA = lane & 15, kbA = lane >> 4;  // A ldmatrix roles
    // B ldmatrix (non-trans, [n][k]) lane roles:
    const int nloc = (lane & 7) + ((lane >> 4) & 1) * 8;  // row within 16-row group
    const uint32_t kofb = (uint32_t)(((lane >> 3) & 1) * 16); // 16B k-offset

    // ---- zero row 0 of both x buffers ----
    if (tid < 64) {
        *(uint32_t*)(smem + SM_XH + tid * 4) = 0u;
        *(uint32_t*)(smem + SM_XL + tid * 4) = 0u;
    }

    // ---- prefetch A[kk=0] ----
    const int am = tid >> 1, aq = tid & 1;
    {
        const __half* Ac = g_Aexp + ((size_t)(aq * 9 + 0) * 256 + m0 + am) * 128;
        #pragma unroll
        for (int j = 0; j < 16; j++) {
            const uint32_t dst = sb + am * 512 + (uint32_t)(((aq * 16 + j) ^ (am & 7)) * 16);
            CP_ASYNC16(dst, Ac + j * 8);
        }
        CP_COMMIT();
    }

    // ---- stage x once: 3 rows x 128 cin, convert, transpose into [n][k] ----
    {
        #pragma unroll 1
        for (int i = 0; i < 24; i++) {
            const int g = tid + 256 * i;          // 0..6143
            const int row = g >> 4;               // (ky, cin): 0..383
            const int f4i = g & 15;
            const int ky = row >> 7, cin = row & 127;
            const int hh = h0 + ky - 1;
            if (hh < 0 || hh > 63) continue;
            float4 v = *(const float4*)(x + (((size_t)b * 128 + cin) * 64 + hh) * 64 + f4i * 4);
            float fv[4] = {v.x, v.y, v.z, v.w};
            const uint32_t colh = (uint32_t)(cin >> 3);
            const uint32_t cofs = (uint32_t)((cin & 7) * 2);
            #pragma unroll
            for (int e = 0; e < 4; e++) {
                const int n = f4i * 4 + e;
                const int smrow = 1 + ky * 64 + n;
                const uint32_t ad = (uint32_t)(smrow * 256) +
                                    ((colh ^ (uint32_t)(smrow & 7)) * 16) + cofs;
                __half hi = __float2half_rn(fv[e]);
                __half lo = __float2half_rn((fv[e] - __half2float(hi)) * 2048.0f);
                *(__half*)(smem + SM_XH + ad) = hi;
                *(__half*)(smem + SM_XL + ad) = lo;
            }
        }
    }

    // ---- main loop over 9 taps ----
    #pragma unroll 1
    for (int kk = 0; kk < 9; kk++) {
        CP_WAIT0();
        __syncthreads();   // A[kk&1] visible; prior reads of other buffer done; x visible (kk=0)

        if (kk < 9 - 1) {  // prefetch A[kk+1] into other buffer
            const __half* Ac = g_Aexp + ((size_t)(aq * 9 + kk + 1) * 256 + m0 + am) * 128;
            const uint32_t abuf = (uint32_t)(((kk + 1) & 1) * 65536);
            #pragma unroll
            for (int j = 0; j < 16; j++) {
                const uint32_t dst = sb + abuf + am * 512 +
                                     (uint32_t)(((aq * 16 + j) ^ (am & 7)) * 16);
                CP_ASYNC16(dst, Ac + j * 8);
            }
            CP_COMMIT();
        }

        const int ky = kk / 3, kx = kk % 3;
        const bool hvalid = (h0 + ky - 1 >= 0) && (h0 + ky - 1 < 64);
        const uint32_t abase = sb + (uint32_t)((kk & 1) * 65536);

        // per-lane B row addresses for this (ky,kx)
        uint32_t baseH[2], par16[2];
        #pragma unroll
        for (int p = 0; p < 2; p++) {
            const int w = wn * 32 + p * 16 + nloc + kx - 1;
            const int rowidx = (hvalid && w >= 0 && w < 64) ? (1 + ky * 64 + w) : 0;
            baseH[p] = sb + SM_XH + (uint32_t)(rowidx * 256);
            par16[p] = (uint32_t)((rowidx & 7) * 16);
        }

        #pragma unroll
        for (int ks = 0; ks < 8; ks++) {
            uint32_t ahi[2][4], alo[2][4];
            #pragma unroll
            for (int mt = 0; mt < 2; mt++) {
                const int m = wm * 32 + mt * 16 + mlA;
                const uint32_t rbase = abase + (uint32_t)(m * 512);
                const uint32_t chi = (uint32_t)(((ks * 2 + kbA) ^ (m & 7)) * 16);
                const uint32_t clo = (uint32_t)(((16 + ks * 2 + kbA) ^ (m & 7)) * 16);
                LDMX4(ahi[mt][0], ahi[mt][1], ahi[mt][2], ahi[mt][3], rbase + chi);
                LDMX4(alo[mt][0], alo[mt][1], alo[mt][2], alo[mt][3], rbase + clo);
            }
            #pragma unroll
            for (int p = 0; p < 2; p++) {
                const uint32_t adH = baseH[p] + (((uint32_t)(ks * 32) + kofb) ^ par16[p]);
                uint32_t bh[4], bl[4];
                LDMX4(bh[0], bh[1], bh[2], bh[3], adH);
                LDMX4(bl[0], bl[1], bl[2], bl[3], adH + XL_DELTA);
                #pragma unroll
                for (int mt = 0; mt < 2; mt++) {
                    MMA16816(acc1[mt][p * 2],     ahi[mt], bh[0], bh[1]);
                    MMA16816(acc1[mt][p * 2 + 1], ahi[mt], bh[2], bh[3]);
                    MMA16816(acc2[mt][p * 2],     alo[mt], bh[0], bh[1]);
                    MMA16816(acc2[mt][p * 2 + 1], alo[mt], bh[2], bh[3]);
                    MMA16816(acc2[mt][p * 2],     ahi[mt], bl[0], bl[1]);
                    MMA16816(acc2[mt][p * 2 + 1], ahi[mt], bl[2], bl[3]);
                }
            }
        }
    }

    // ---- epilogue: combine and write conv scratch ----
    const float RS = 4.8828125e-4f;   // 2^-11
    #pragma unroll
    for (int mt = 0; mt < 2; mt++) {
        const int co = m0 + wm * 32 + mt * 16 + (lane >> 2);
        float* dst = g_conv + (((size_t)b * 256 + co) * 64 + h0) * 64;
        #pragma unroll
        for (int nt = 0; nt < 4; nt++) {
            const int n = wn * 32 + nt * 8 + (lane & 3) * 2;
            float2 v01 = make_float2(acc1[mt][nt][0] + acc2[mt][nt][0] * RS,
                                     acc1[mt][nt][1] + acc2[mt][nt][1] * RS);
            float2 v23 = make_float2(acc1[mt][nt][2] + acc2[mt][nt][2] * RS,
                                     acc1[mt][nt][3] + acc2[mt][nt][3] * RS);
            *(float2*)(dst + n) = v01;
            *(float2*)(dst + 8 * 4096 + n) = v23;   // co + 8
        }
    }
}

// ---------------- topk: noise + 64th-largest + bias + relu ----------------
#define OS_FLOATS (64 * 257)
#define TOPK_SMEM ((OS_FLOATS + 64) * 4)

__global__ __launch_bounds__(512, 1)
void topk_kernel(const float* __restrict__ noise,
                 const float* __restrict__ relu_bias,
                 float* __restrict__ out) {
    extern __shared__ float sm[];
    float* os = sm;                                  // [w][257]
    unsigned* th = (unsigned*)(sm + OS_FLOATS);      // [64]

    const int bh = blockIdx.x;
    const int b = bh >> 6;
    const int h = bh & 63;
    const int tid = threadIdx.x;
    const int wid = tid >> 5, lane = tid & 31;

    {
        const float* cb = g_conv + (size_t)b * 256 * 4096 + h * 64;
        const float* nb = noise + (size_t)b * 256 * 4096 + h * 64;
        for (int idx = tid; idx < 256 * 64; idx += 512) {
            int c = idx >> 6, w = idx & 63;
            float u = nb[c * 4096 + w];
            os[w * 257 + c] = cb[c * 4096 + w] + g_bias[c] * NOISE_SCALE * (2.0f * u - 1.0f);
        }
    }
    __syncthreads();

    #pragma unroll 1
    for (int pp = 0; pp < 4; pp++) {
        const int p = wid * 4 + pp;
        unsigned uv[8];
        #pragma unroll
        for (int j = 0; j < 8; j++)
            uv[j] = ordmap(os[p * 257 + lane * 8 + j]);
        unsigned X = 0;
        #pragma unroll 1
        for (int bit = 31; bit >= 0; bit--) {
            unsigned cand = X | (1u << bit);
            int cnt = 0;
            #pragma unroll
            for (int j = 0; j < 8; j++) cnt += (uv[j] >= cand) ? 1 : 0;
            int tot = __reduce_add_sync(0xffffffffu, cnt);
            if (tot >= K_SEL) X = cand;
        }
        if (lane == 0) th[p] = X;
    }
    __syncthreads();

    {
        float* ob = out + (size_t)b * 256 * 4096 + h * 64;
        for (int idx = tid; idx < 256 * 64; idx += 512) {
            int c = idx >> 6, w = idx & 63;
            float v = os[w * 257 + c];
            float keep = (ordmap(v) >= th[w]) ? v : 0.f;
            ob[c * 4096 + w] = fmaxf(keep + __ldg(relu_bias + c), 0.f);
        }
    }
}

// ---------------- launch ----------------
extern "C" void kernel_launch(void* const* d_in, const int* in_sizes, int n_in,
                              void* d_out, int out_size) {
    const float* x         = (const float*)d_in[0];
    const float* weight    = (const float*)d_in[1];
    const float* relu_bias = (const float*)d_in[2];
    const float* noise     = (const float*)d_in[3];
    float* out = (float*)d_out;

    bias_kernel<<<256, 128>>>(weight);
    wexpand_kernel<<<256, 256>>>(weight);

    cudaFuncSetAttribute(conv_kernel,
                         cudaFuncAttributeMaxDynamicSharedMemorySize, CONV_SMEM);
    conv_kernel<<<dim3(2, 64, 32), 256, CONV_SMEM>>>(x);

    cudaFuncSetAttribute(topk_kernel,
                         cudaFuncAttributeMaxDynamicSharedMemorySize, TOPK_SMEM);
    topk_kernel<<<2048, 512, TOPK_SMEM>>>(noise, relu_bias, out);
}

// round 13
// speedup vs baseline: 3.5347x; 1.3979x over previous
#include <cuda_runtime.h>
#include <cuda_fp16.h>
#include <cstdint>

#define NOISE_SCALE (8.0f/255.0f)
#define K_SEL 64

__device__ float g_bias[256];
__device__ __half g_Aexp[2 * 9 * 256 * 128];          // [comp][kk][cout][cin]
__device__ float g_conv[(size_t)32 * 256 * 64 * 64];  // conv scratch (NCHW)

// ---------------- conv smem layout (bytes) ----------------
#define SM_AH  0                       // whi  [128 m][128 k] halves, 256B rows = 32KB
#define SM_AL  32768                   // wlo' [128 m][128 k] halves           = 32KB
#define SM_XH  65536                   // xh: 257 rows x 256B (row 0 zeros)    = 65792
#define SM_XL  131328                  // xl': 257 rows x 256B                 = 65792
#define XL_DELTA 65792
#define CONV_SMEM 197120               // 192.5KB

__device__ __forceinline__ uint32_t smem_u32(const void* p) {
    uint32_t a;
    asm("{ .reg .u64 t; cvta.to.shared.u64 t, %1; cvt.u32.u64 %0, t; }" : "=r"(a) : "l"(p));
    return a;
}
__device__ __forceinline__ unsigned ordmap(float f) {
    int s = __float_as_int(f);
    return (unsigned)(s ^ ((s >> 31) | 0x80000000));
}

#define CP_ASYNC16(dst, src) \
    asm volatile("cp.async.ca.shared.global [%0], [%1], 16;" :: "r"(dst), "l"(src))
#define CP_COMMIT() asm volatile("cp.async.commit_group;" ::: "memory")
#define CP_WAIT0()  asm volatile("cp.async.wait_group 0;" ::: "memory")

#define LDMX4(r0,r1,r2,r3,ad) \
    asm volatile("ldmatrix.sync.aligned.m8n8.x4.shared.b16 {%0,%1,%2,%3}, [%4];" \
        : "=r"(r0),"=r"(r1),"=r"(r2),"=r"(r3) : "r"(ad))
#define MMA16816(c, a, b0v, b1v) \
    asm volatile("mma.sync.aligned.m16n8k16.row.col.f32.f16.f16.f32 " \
        "{%0,%1,%2,%3}, {%4,%5,%6,%7}, {%8,%9}, {%0,%1,%2,%3};" \
        : "+f"((c)[0]), "+f"((c)[1]), "+f"((c)[2]), "+f"((c)[3]) \
        : "r"((a)[0]), "r"((a)[1]), "r"((a)[2]), "r"((a)[3]), "r"(b0v), "r"(b1v))

// ---------------- prep: g_bias[c] = sum |w[c,:,:,:]| ----------------
__global__ void bias_kernel(const float* __restrict__ w) {
    int c = blockIdx.x, t = threadIdx.x;
    float s = 0.f;
    #pragma unroll
    for (int k = 0; k < 9; k++) s += fabsf(w[c * 1152 + k * 128 + t]);
    __shared__ float red[128];
    red[t] = s;
    __syncthreads();
    #pragma unroll
    for (int off = 64; off > 0; off >>= 1) {
        if (t < off) red[t] += red[t + off];
        __syncthreads();
    }
    if (t == 0) g_bias[c] = red[0];
}

// ---------------- prep: fp16 hi/lo split weights ----------------
__global__ void wexpand_kernel(const float* __restrict__ w) {
    int co = blockIdx.x;
    for (int idx = threadIdx.x; idx < 1152; idx += blockDim.x) {
        int kk = idx >> 7, cin = idx & 127;
        float v = w[co * 1152 + cin * 9 + kk];
        __half hi = __float2half_rn(v);
        __half lo = __float2half_rn((v - __half2float(hi)) * 2048.0f);
        g_Aexp[((size_t)kk * 256 + co) * 128 + cin] = hi;
        g_Aexp[(size_t)9 * 256 * 128 + ((size_t)kk * 256 + co) * 128 + cin] = lo;
    }
}

// ---------------- conv: M=128 x N=128 stage-once fp16 mma.sync --------------
__global__ __launch_bounds__(256)
void conv_kernel(const float* __restrict__ x) {
    extern __shared__ char smem[];
    const uint32_t sb = smem_u32(smem);
    const int tid = threadIdx.x;
    const int wid = tid >> 5, lane = tid & 31;
    const int wm = wid & 3, wn = wid >> 2;       // 4 M-warps x 2 N-warps (N tile 64)
    const int mhalf = blockIdx.x;                // 0-1
    const int h0 = blockIdx.y * 2;               // 2 image rows per CTA
    const int b = blockIdx.z;                    // 0-31
    const int m0 = mhalf * 128;

    float acc1[2][8][4], acc2[2][8][4];
    #pragma unroll
    for (int i = 0; i < 2; i++)
        #pragma unroll
        for (int j = 0; j < 8; j++)
            #pragma unroll
            for (int k = 0; k < 4; k++) { acc1[i][j][k] = 0.f; acc2[i][j][k] = 0.f; }

    const int mlA = lane & 15, kbA = lane >> 4;               // A ldmatrix roles
    const int nloc = (lane & 7) + ((lane >> 4) & 1) * 8;      // B row-in-16 group
    const uint32_t kofb = (uint32_t)(((lane >> 3) & 1) * 16); // B 16B k-offset

    // ---- zero row 0 of both x buffers ----
    if (tid < 64) {
        *(uint32_t*)(smem + SM_XH + tid * 4) = 0u;
        *(uint32_t*)(smem + SM_XL + tid * 4) = 0u;
    }

    // ---- A staging roles; prefetch whi(kk=0) ----
    const int am = tid >> 1, aq = tid & 1;       // row am, k-half aq
    {
        const __half* Ac = g_Aexp + ((size_t)0 * 256 + m0 + am) * 128 + aq * 64;
        #pragma unroll
        for (int j = 0; j < 8; j++) {
            const uint32_t dst = sb + SM_AH + am * 256 +
                                 (uint32_t)(((aq * 8 + j) ^ (am & 7)) * 16);
            CP_ASYNC16(dst, Ac + j * 8);
        }
        CP_COMMIT();
    }

    // ---- stage x once: 4 image rows (h0-1..h0+2) x 128 cin, transposed ----
    {
        #pragma unroll 1
        for (int i = 0; i < 32; i++) {
            const int g = tid + 256 * i;          // 0..8191
            const int row = g >> 4;               // (slot, cin): 0..511
            const int f4i = g & 15;
            const int s = row >> 7, cin = row & 127;
            const int hh = h0 - 1 + s;
            if (hh < 0 || hh > 63) continue;
            float4 v = *(const float4*)(x + (((size_t)b * 128 + cin) * 64 + hh) * 64 + f4i * 4);
            float fv[4] = {v.x, v.y, v.z, v.w};
            const uint32_t colh = (uint32_t)(cin >> 3);
            const uint32_t cofs = (uint32_t)((cin & 7) * 2);
            #pragma unroll
            for (int e = 0; e < 4; e++) {
                const int w = f4i * 4 + e;
                const int smrow = 1 + s * 64 + w;
                const uint32_t ad = (uint32_t)(smrow * 256) +
                                    ((colh ^ (uint32_t)(smrow & 7)) * 16) + cofs;
                __half hi = __float2half_rn(fv[e]);
                __half lo = __float2half_rn((fv[e] - __half2float(hi)) * 2048.0f);
                *(__half*)(smem + SM_XH + ad) = hi;
                *(__half*)(smem + SM_XL + ad) = lo;
            }
        }
    }

    // ---- main loop over 9 taps ----
    #pragma unroll 1
    for (int kk = 0; kk < 9; kk++) {
        const int ky = kk / 3, kx = kk % 3;

        CP_WAIT0();
        __syncthreads();   // whi(kk) ready; x ready (kk=0); prior wlo reads done

        // prefetch wlo'(kk)
        {
            const __half* Ac = g_Aexp + (size_t)9 * 256 * 128
                             + ((size_t)kk * 256 + m0 + am) * 128 + aq * 64;
            #pragma unroll
            for (int j = 0; j < 8; j++) {
                const uint32_t dst = sb + SM_AL + am * 256 +
                                     (uint32_t)(((aq * 8 + j) ^ (am & 7)) * 16);
                CP_ASYNC16(dst, Ac + j * 8);
            }
            CP_COMMIT();
        }

        // per-lane B row addresses for this tap (r = wn)
        uint32_t baseH[4], par16[4];
        {
            const int hh = h0 + wn + ky - 1;
            const bool hv = (hh >= 0) && (hh < 64);
            const int s = wn + ky;
            #pragma unroll
            for (int p = 0; p < 4; p++) {
                const int w = p * 16 + nloc + kx - 1;
                const int rowidx = (hv && w >= 0 && w < 64) ? (1 + s * 64 + w) : 0;
                baseH[p] = sb + SM_XH + (uint32_t)(rowidx * 256);
                par16[p] = (uint32_t)((rowidx & 7) * 16);
            }
        }

        // ---- phase A: whi x (xh -> acc1, xl' -> acc2) ----
        #pragma unroll
        for (int ks = 0; ks < 8; ks++) {
            uint32_t ahi[2][4];
            #pragma unroll
            for (int mt = 0; mt < 2; mt++) {
                const int m = wm * 32 + mt * 16 + mlA;
                const uint32_t c = (uint32_t)(((ks * 2 + kbA) ^ (m & 7)) * 16);
                LDMX4(ahi[mt][0], ahi[mt][1], ahi[mt][2], ahi[mt][3],
                      sb + SM_AH + (uint32_t)(m * 256) + c);
            }
            #pragma unroll
            for (int p = 0; p < 4; p++) {
                const uint32_t adH = baseH[p] + (((uint32_t)(ks * 32) + kofb) ^ par16[p]);
                uint32_t bh[4], bl[4];
                LDMX4(bh[0], bh[1], bh[2], bh[3], adH);
                LDMX4(bl[0], bl[1], bl[2], bl[3], adH + XL_DELTA);
                #pragma unroll
                for (int mt = 0; mt < 2; mt++) {
                    MMA16816(acc1[mt][p * 2],     ahi[mt], bh[0], bh[1]);
                    MMA16816(acc1[mt][p * 2 + 1], ahi[mt], bh[2], bh[3]);
                    MMA16816(acc2[mt][p * 2],     ahi[mt], bl[0], bl[1]);
                    MMA16816(acc2[mt][p * 2 + 1], ahi[mt], bl[2], bl[3]);
                }
            }
        }

        CP_WAIT0();
        __syncthreads();   // wlo'(kk) ready; phase-A reads of SM_AH done

        // prefetch whi(kk+1)
        if (kk < 8) {
            const __half* Ac = g_Aexp + ((size_t)(kk + 1) * 256 + m0 + am) * 128 + aq * 64;
            #pragma unroll
            for (int j = 0; j < 8; j++) {
                const uint32_t dst = sb + SM_AH + am * 256 +
                                     (uint32_t)(((aq * 8 + j) ^ (am & 7)) * 16);
                CP_ASYNC16(dst, Ac + j * 8);
            }
            CP_COMMIT();
        }

        // ---- phase B: wlo' x xh -> acc2 ----
        #pragma unroll
        for (int ks = 0; ks < 8; ks++) {
            uint32_t alo[2][4];
            #pragma unroll
            for (int mt = 0; mt < 2; mt++) {
                const int m = wm * 32 + mt * 16 + mlA;
                const uint32_t c = (uint32_t)(((ks * 2 + kbA) ^ (m & 7)) * 16);
                LDMX4(alo[mt][0], alo[mt][1], alo[mt][2], alo[mt][3],
                      sb + SM_AL + (uint32_t)(m * 256) + c);
            }
            #pragma unroll
            for (int p = 0; p < 4; p++) {
                const uint32_t adH = baseH[p] + (((uint32_t)(ks * 32) + kofb) ^ par16[p]);
                uint32_t bh[4];
                LDMX4(bh[0], bh[1], bh[2], bh[3], adH);
                #pragma unroll
                for (int mt = 0; mt < 2; mt++) {
                    MMA16816(acc2[mt][p * 2],     alo[mt], bh[0], bh[1]);
                    MMA16816(acc2[mt][p * 2 + 1], alo[mt], bh[2], bh[3]);
                }
            }
        }
    }

    // ---- epilogue: combine and write conv scratch (row h0+wn) ----
    const float RS = 4.8828125e-4f;   // 2^-11
    #pragma unroll
    for (int mt = 0; mt < 2; mt++) {
        const int co = m0 + wm * 32 + mt * 16 + (lane >> 2);
        float* dst = g_conv + (((size_t)b * 256 + co) * 64 + (h0 + wn)) * 64;
        #pragma unroll
        for (int nt = 0; nt < 8; nt++) {
            const int n = nt * 8 + (lane & 3) * 2;
            float2 v01 = make_float2(acc1[mt][nt][0] + acc2[mt][nt][0] * RS,
                                     acc1[mt][nt][1] + acc2[mt][nt][1] * RS);
            float2 v23 = make_float2(acc1[mt][nt][2] + acc2[mt][nt][2] * RS,
                                     acc1[mt][nt][3] + acc2[mt][nt][3] * RS);
            *(float2*)(dst + n) = v01;
            *(float2*)(dst + 8 * 4096 + n) = v23;   // co + 8
        }
    }
}

// ---------------- topk: noise + 64th-largest + bias + relu ----------------
#define OS_FLOATS (64 * 257)
#define TOPK_SMEM ((OS_FLOATS + 64) * 4)

__global__ __launch_bounds__(512, 1)
void topk_kernel(const float* __restrict__ noise,
                 const float* __restrict__ relu_bias,
                 float* __restrict__ out) {
    extern __shared__ float sm[];
    float* os = sm;                                  // [w][257]
    unsigned* th = (unsigned*)(sm + OS_FLOATS);      // [64]

    const int bh = blockIdx.x;
    const int b = bh >> 6;
    const int h = bh & 63;
    const int tid = threadIdx.x;
    const int wid = tid >> 5, lane = tid & 31;

    {
        const float* cb = g_conv + (size_t)b * 256 * 4096 + h * 64;
        const float* nb = noise + (size_t)b * 256 * 4096 + h * 64;
        for (int idx = tid; idx < 256 * 64; idx += 512) {
            int c = idx >> 6, w = idx & 63;
            float u = nb[c * 4096 + w];
            os[w * 257 + c] = cb[c * 4096 + w] + g_bias[c] * NOISE_SCALE * (2.0f * u - 1.0f);
        }
    }
    __syncthreads();

    #pragma unroll 1
    for (int pp = 0; pp < 4; pp++) {
        const int p = wid * 4 + pp;
        unsigned uv[8];
        #pragma unroll
        for (int j = 0; j < 8; j++)
            uv[j] = ordmap(os[p * 257 + lane * 8 + j]);
        unsigned X = 0;
        #pragma unroll 1
        for (int bit = 31; bit >= 0; bit--) {
            unsigned cand = X | (1u << bit);
            int cnt = 0;
            #pragma unroll
            for (int j = 0; j < 8; j++) cnt += (uv[j] >= cand) ? 1 : 0;
            int tot = __reduce_add_sync(0xffffffffu, cnt);
            if (tot >= K_SEL) X = cand;
        }
        if (lane == 0) th[p] = X;
    }
    __syncthreads();

    {
        float* ob = out + (size_t)b * 256 * 4096 + h * 64;
        for (int idx = tid; idx < 256 * 64; idx += 512) {
            int c = idx >> 6, w = idx & 63;
            float v = os[w * 257 + c];
            float keep = (ordmap(v) >= th[w]) ? v : 0.f;
            ob[c * 4096 + w] = fmaxf(keep + __ldg(relu_bias + c), 0.f);
        }
    }
}

// ---------------- launch ----------------
extern "C" void kernel_launch(void* const* d_in, const int* in_sizes, int n_in,
                              void* d_out, int out_size) {
    const float* x         = (const float*)d_in[0];
    const float* weight    = (const float*)d_in[1];
    const float* relu_bias = (const float*)d_in[2];
    const float* noise     = (const float*)d_in[3];
    float* out = (float*)d_out;

    bias_kernel<<<256, 128>>>(weight);
    wexpand_kernel<<<256, 256>>>(weight);

    cudaFuncSetAttribute(conv_kernel,
                         cudaFuncAttributeMaxDynamicSharedMemorySize, CONV_SMEM);
    conv_kernel<<<dim3(2, 32, 32), 256, CONV_SMEM>>>(x);

    cudaFuncSetAttribute(topk_kernel,
                         cudaFuncAttributeMaxDynamicSharedMemorySize, TOPK_SMEM);
    topk_kernel<<<2048, 512, TOPK_SMEM>>>(noise, relu_bias, out);
}